// round 4
// baseline (speedup 1.0000x reference)
#include <cuda_runtime.h>
#include <cstdint>

#define BATCH 32
#define NPTS  65536
#define SSAMP 512
#define CPB   4                 // CTAs per batch = cluster size
#define PSH   (NPTS / CPB)      // 16384 points per CTA shard
#define TPB   512
#define PAIRS (PSH / (2 * TPB)) // 16 point-pairs per thread
#define SPAIR 10                // pairs read from SMEM each iter
#define RPAIR (PAIRS - SPAIR)   // 6 pairs kept in registers
#define PPT   (2 * PAIRS)       // 32 points per thread

__device__ int g_idx[BATCH][SSAMP];

// ---- packed f32x2 helpers (IEEE-identical to scalar ops) ----
#define ADD_F32X2(out, a, b) \
    asm("add.rn.f32x2 %0, %1, %2;" : "=l"(out) : "l"(a), "l"(b))
#define MUL_F32X2(out, a, b) \
    asm("mul.rn.f32x2 %0, %1, %2;" : "=l"(out) : "l"(a), "l"(b))
#define FMA_F32X2(out, a, b, c) \
    asm("fma.rn.f32x2 %0, %1, %2, %3;" : "=l"(out) : "l"(a), "l"(b), "l"(c))
#define PACK_F32X2(out, lo, hi) \
    asm("mov.b64 %0, {%1, %2;}" : "=l"(out) : "r"(lo), "r"(hi))
#define PACK_F32X2_OK(out, lo, hi) \
    asm("mov.b64 %0, {%1, %2};" : "=l"(out) : "r"(lo), "r"(hi))
#define UNPACK_F32X2(lo, hi, in) \
    asm("mov.b64 {%0, %1}, %2;" : "=r"(lo), "=r"(hi) : "l"(in))

__global__ void __launch_bounds__(TPB, 1) __cluster_dims__(CPB, 1, 1)
fps_kernel(const float* __restrict__ xyz) {
    extern __shared__ float sm[];
    const int cta  = blockIdx.x;
    const int b    = cta >> 2;          // batch
    const int c    = cta & 3;           // rank in cluster
    const int base = c * PSH;
    const int t    = threadIdx.x;
    const float* X = xyz + (size_t)b * NPTS * 3;

    float* xs = sm;
    float* ys = sm + PSH;
    float* zs = sm + 2 * PSH;
    unsigned long long* red = (unsigned long long*)(sm + 3 * PSH); // 16 keys
    char* ex = (char*)(red + 16);       // 2 parity x 4 rank x 32B slots
    unsigned long long* mbar = (unsigned long long*)(ex + 2 * CPB * 32);

    // Load shard, deinterleave [P,3] -> SoA (coalesced, one-time).
    for (int i = t; i < 3 * PSH; i += TPB) {
        float v = X[(size_t)base * 3 + i];
        int p = i / 3;
        int k = i - 3 * p;
        sm[k * PSH + p] = v;
    }

    uint32_t mbar_base = (uint32_t)__cvta_generic_to_shared(mbar);
    if (t == 0) {
        asm volatile("mbarrier.init.shared.b64 [%0], %1;"
                     :: "r"(mbar_base), "r"((unsigned)CPB) : "memory");
        asm volatile("mbarrier.init.shared.b64 [%0], %1;"
                     :: "r"(mbar_base + 8), "r"((unsigned)CPB) : "memory");
    }
    __syncthreads();
    asm volatile("barrier.cluster.arrive.aligned;" ::: "memory");
    asm volatile("barrier.cluster.wait.aligned;" ::: "memory");

    const unsigned long long* xs2 = (const unsigned long long*)xs;
    const unsigned long long* ys2 = (const unsigned long long*)ys;
    const unsigned long long* zs2 = (const unsigned long long*)zs;

    // register-resident pairs: [SPAIR, PAIRS)
    unsigned long long rx[RPAIR], ry[RPAIR], rz[RPAIR];
#pragma unroll
    for (int j = 0; j < RPAIR; j++) {
        int q = t + (SPAIR + j) * TPB;
        rx[j] = xs2[q]; ry[j] = ys2[q]; rz[j] = zs2[q];
    }

    float dist[PPT];
#pragma unroll
    for (int j = 0; j < PPT; j++) dist[j] = 1e10f;

    float cx = X[0], cy = X[1], cz = X[2];   // first centroid = point 0
    if (c == 0 && t == 0) g_idx[b][0] = 0;

    uint32_t ex_base = (uint32_t)__cvta_generic_to_shared(ex);

    for (int iter = 0; iter < SSAMP - 1; iter++) {
        const int par = iter & 1;
        const unsigned ph = (unsigned)((iter >> 1) & 1);
        unsigned long long ncx2, ncy2, ncz2;
        {
            uint32_t nx = __float_as_uint(-cx);
            uint32_t ny = __float_as_uint(-cy);
            uint32_t nz = __float_as_uint(-cz);
            PACK_F32X2_OK(ncx2, nx, nx);
            PACK_F32X2_OK(ncy2, ny, ny);
            PACK_F32X2_OK(ncz2, nz, nz);
        }

        // --- scan: packed distance update; 4 independent max accumulators ---
        float b0 = -1.0f, b1 = -1.0f, b2m = -1.0f, b3m = -1.0f;
#pragma unroll
        for (int jj = 0; jj < PAIRS; jj++) {
            int q = t + jj * TPB;
            unsigned long long x2, y2, z2;
            if (jj < SPAIR) { x2 = xs2[q]; y2 = ys2[q]; z2 = zs2[q]; }
            else { x2 = rx[jj - SPAIR]; y2 = ry[jj - SPAIR]; z2 = rz[jj - SPAIR]; }
            unsigned long long dx2, dy2, dz2, s2;
            ADD_F32X2(dx2, x2, ncx2);
            ADD_F32X2(dy2, y2, ncy2);
            ADD_F32X2(dz2, z2, ncz2);
            MUL_F32X2(s2, dx2, dx2);
            FMA_F32X2(s2, dy2, dy2, s2);
            FMA_F32X2(s2, dz2, dz2, s2);
            uint32_t lo, hi;
            UNPACK_F32X2(lo, hi, s2);
            float v0 = fminf(dist[2 * jj],     __uint_as_float(lo));
            float v1 = fminf(dist[2 * jj + 1], __uint_as_float(hi));
            dist[2 * jj]     = v0;
            dist[2 * jj + 1] = v1;
            if (jj & 1) { b2m = fmaxf(b2m, v0); b3m = fmaxf(b3m, v1); }
            else        { b0  = fmaxf(b0,  v0); b1  = fmaxf(b1,  v1); }
        }
        float bv = fmaxf(fmaxf(b0, b1), fmaxf(b2m, b3m));

        // locate smallest k with dist[k]==bv via mask (independent ops + ffs);
        // p(k) = 2t + (k&~1)*TPB + (k&1) is monotone in k -> smallest index.
        unsigned m0 = 0, m1 = 0;
#pragma unroll
        for (int k = 0; k < 16; k++)
            m0 |= (dist[k] == bv) ? (1u << k) : 0u;
#pragma unroll
        for (int k = 16; k < 32; k++)
            m1 |= (dist[k] == bv) ? (1u << (k - 16)) : 0u;
        int k0 = m0 ? (__ffs(m0) - 1) : (__ffs(m1) + 15);
        int bp = 2 * t + (k0 & ~1) * TPB + (k0 & 1);

        unsigned long long key =
            ((unsigned long long)__float_as_uint(bv) << 32) |
            (unsigned)(~(unsigned)(base + bp));

#pragma unroll
        for (int o = 16; o; o >>= 1) {
            unsigned long long other = __shfl_xor_sync(0xffffffffu, key, o);
            if (other > key) key = other;
        }
        if ((t & 31) == 0) red[t >> 5] = key;
        __syncthreads();

        // warp 0: reduce 16 warp keys, push candidate to all 4 ranks
        if (t < 32) {
            unsigned long long k2 = red[t & 15];
#pragma unroll
            for (int o = 8; o; o >>= 1) {
                unsigned long long other = __shfl_xor_sync(0xffffffffu, k2, o);
                if (other > k2) k2 = other;
            }
            int widx = (int)(~(unsigned)k2);
            int off  = widx - base;
            float wx = xs[off], wy = ys[off], wz = zs[off];  // broadcast LDS
            if (t < CPB) {
                uint32_t lslot = ex_base + (uint32_t)(par * CPB + c) * 32u;
                uint32_t raddr, rmbar;
                asm("mapa.shared::cluster.u32 %0, %1, %2;"
                    : "=r"(raddr) : "r"(lslot), "r"(t));
                asm("mapa.shared::cluster.u32 %0, %1, %2;"
                    : "=r"(rmbar) : "r"(mbar_base + (uint32_t)par * 8u), "r"(t));
                unsigned long long xy;
                PACK_F32X2_OK(xy, __float_as_uint(wx), __float_as_uint(wy));
                asm volatile("st.shared::cluster.u64 [%0], %1;"
                             :: "r"(raddr), "l"(k2) : "memory");
                asm volatile("st.shared::cluster.u64 [%0+8], %1;"
                             :: "r"(raddr), "l"(xy) : "memory");
                asm volatile("st.shared::cluster.u32 [%0+16], %1;"
                             :: "r"(raddr), "r"(__float_as_uint(wz)) : "memory");
                asm volatile(
                    "mbarrier.arrive.release.cluster.shared::cluster.b64 _, [%0];"
                    :: "r"(rmbar) : "memory");
            }
        }

        // wait on LOCAL parity mbarrier (acquire, cluster scope)
        {
            uint32_t mb = mbar_base + (uint32_t)par * 8u;
            uint32_t done;
            do {
                asm volatile(
                    "{\n\t.reg .pred p;\n\t"
                    "mbarrier.try_wait.parity.acquire.cluster.shared::cta.b64 p, [%1], %2;\n\t"
                    "selp.b32 %0, 1, 0, p;\n\t}"
                    : "=r"(done) : "r"(mb), "r"(ph) : "memory");
            } while (!done);
        }

        // every thread reduces the 4 candidates locally (broadcast LDS)
        {
            const unsigned long long* slots =
                (const unsigned long long*)(ex + par * CPB * 32);
            unsigned long long kb = slots[0];
            int rb = 0;
            unsigned long long ka = slots[4], kc = slots[8], kd = slots[12];
            if (ka > kb) { kb = ka; rb = 1; }
            if (kc > kb) { kb = kc; rb = 2; }
            if (kd > kb) { kb = kd; rb = 3; }
            const float* sp = (const float*)(ex + (par * CPB + rb) * 32 + 8);
            cx = sp[0]; cy = sp[1]; cz = sp[2];
            if (c == 0 && t == 0)
                g_idx[b][iter + 1] = (int)(~(unsigned)kb);
        }
    }
}

// Gather: out = [B,S,3] xyz_sampled then [B,S,64] f_sampled. float4 copies.
__global__ void gather_kernel(const float* __restrict__ xyz,
                              const float* __restrict__ f,
                              float* __restrict__ out) {
    int r    = blockIdx.x * 4 + (threadIdx.x >> 4);  // row 0 .. B*S-1
    int lane = threadIdx.x & 15;
    int b = r >> 9;
    int j = r & (SSAMP - 1);
    int idx = g_idx[b][j];
    const float4* fr = (const float4*)(f + ((size_t)b * NPTS + idx) * 64);
    float4* fo = (float4*)(out + (size_t)BATCH * SSAMP * 3 +
                           ((size_t)b * SSAMP + j) * 64);
    fo[lane] = fr[lane];
    if (lane < 3) {
        out[((size_t)b * SSAMP + j) * 3 + lane] =
            xyz[((size_t)b * NPTS + idx) * 3 + lane];
    }
}

extern "C" void kernel_launch(void* const* d_in, const int* in_sizes, int n_in,
                              void* d_out, int out_size) {
    const float* xyz = (const float*)d_in[0];
    const float* f   = (const float*)d_in[1];
    float* out = (float*)d_out;

    size_t smem = 3u * PSH * sizeof(float)
                + 16 * sizeof(unsigned long long)
                + 2 * CPB * 32
                + 2 * sizeof(unsigned long long);
    cudaFuncSetAttribute(fps_kernel,
                         cudaFuncAttributeMaxDynamicSharedMemorySize, (int)smem);

    fps_kernel<<<BATCH * CPB, TPB, smem>>>(xyz);
    gather_kernel<<<(BATCH * SSAMP) / 4, 64>>>(xyz, f, out);
}